// round 11
// baseline (speedup 1.0000x reference)
#include <cuda_runtime.h>

// ---------------- problem constants ----------------
constexpr int B_  = 65536;
constexpr int D_  = 256;
constexpr int W1ROWS = 512;         // att_w1 bf16x2: 8 words used, padded to 12 (3x16B units, gcd(3,8)=1 -> conflict-free)
constexpr int W1PADW = 12;
constexpr int P1ROWS = 768;         // pred_w1 bf16x2: 4 words (16B) per row

constexpr int TPB  = 192;           // 6 warps / block
constexpr int WPB  = TPB / 32;
constexpr int GRID = 444;           // 3 blocks/SM -> 18 warps/SM (regs capped at 113)

// dynamic shared layout (word offsets)
constexpr int OFF_W1B = 0;                         // 512*12 = 6144 words
constexpr int OFF_P1B = OFF_W1B + W1ROWS * W1PADW; // 6144
constexpr int OFF_B1  = OFF_P1B + P1ROWS * 4;      // 9216
constexpr int OFF_W2  = OFF_B1 + 16;
constexpr int OFF_PB1 = OFF_W2 + 16;
constexpr int OFF_PW2 = OFF_PB1 + 8;
constexpr int OFF_SC  = OFF_PW2 + 8;
constexpr int SMEM_WORDS = OFF_SC + 8;             // 9272
constexpr int SMEM_BYTES = SMEM_WORDS * 4;         // ~36.2 KB; 3 blocks = 108.6KB/SM

// ---------------- packed f32x2 helpers ----------------
__device__ __forceinline__ unsigned long long splat2(float x) {
    unsigned long long r;
    asm("mov.b64 %0, {%1, %1};" : "=l"(r) : "f"(x));
    return r;
}
__device__ __forceinline__ unsigned long long pack2u(unsigned x, unsigned y) {
    unsigned long long r;
    asm("mov.b64 %0, {%1, %2};" : "=l"(r) : "r"(x), "r"(y));
    return r;
}
__device__ __forceinline__ void ffma2(unsigned long long& d, unsigned long long a, unsigned long long b) {
    asm("fma.rn.f32x2 %0, %1, %2, %0;" : "+l"(d) : "l"(a), "l"(b));
}
__device__ __forceinline__ float lo2(unsigned long long v) { return __uint_as_float((unsigned)v); }
__device__ __forceinline__ float hi2(unsigned long long v) { return __uint_as_float((unsigned)(v >> 32)); }

// bf16x2 word -> packed f32x2 (lo bf16 -> lo f32, hi bf16 -> hi f32)
__device__ __forceinline__ unsigned long long bf2f2(unsigned w) {
    return pack2u(w << 16, w & 0xffff0000u);
}
__device__ __forceinline__ unsigned f2bf2(float f0, float f1) {
    unsigned r;
    asm("cvt.rn.bf16x2.f32 %0, %1, %2;" : "=r"(r) : "f"(f1), "f"(f0));
    return r;
}

// Distributed reduce over 8 values: lane holds p[0..7] partials; returns the
// full 32-lane sum for o=(lane>>2)&7, replicated on each 4-lane o-group.
__device__ __forceinline__ float dreduce8(float* p, unsigned lane) {
    const unsigned FULL = 0xffffffffu;
    const bool b4 = (lane & 16), b3 = (lane & 8), b2 = (lane & 4);
#pragma unroll
    for (int j = 0; j < 4; j++) {
        float send = b4 ? p[j] : p[j + 4];
        float r = __shfl_xor_sync(FULL, send, 16);
        p[j] = (b4 ? p[j + 4] : p[j]) + r;
    }
#pragma unroll
    for (int j = 0; j < 2; j++) {
        float send = b3 ? p[j] : p[j + 2];
        float r = __shfl_xor_sync(FULL, send, 8);
        p[j] = (b3 ? p[j + 2] : p[j]) + r;
    }
    {
        float send = b2 ? p[0] : p[1];
        float r = __shfl_xor_sync(FULL, send, 4);
        p[0] = (b2 ? p[1] : p[0]) + r;
    }
    p[0] += __shfl_xor_sync(FULL, p[0], 2);
    p[0] += __shfl_xor_sync(FULL, p[0], 1);
    return p[0];
}

// Sum across the 8 o-groups; input identical within each 4-lane o-group.
__device__ __forceinline__ float xsum3(float v) {
    v += __shfl_xor_sync(0xffffffffu, v, 4);
    v += __shfl_xor_sync(0xffffffffu, v, 8);
    v += __shfl_xor_sync(0xffffffffu, v, 16);
    return v;
}

__global__ __launch_bounds__(TPB, 3) void agree_kernel(
    const int*   __restrict__ group_inputs,
    const int*   __restrict__ item_inputs,
    const int*   __restrict__ group_members,
    const float* __restrict__ user_emb,
    const float* __restrict__ item_emb,
    const float* __restrict__ group_emb,
    const float* __restrict__ att_w1,
    const float* __restrict__ att_b1,
    const float* __restrict__ att_w2,
    const float* __restrict__ att_b2,
    const float* __restrict__ cls_w,
    const float* __restrict__ cls_b,
    const float* __restrict__ pred_w1,
    const float* __restrict__ pred_b1,
    const float* __restrict__ pred_w2,
    const float* __restrict__ pred_b2,
    float* __restrict__ out)
{
    extern __shared__ float sm[];
    unsigned* s_w1b = reinterpret_cast<unsigned*>(sm + OFF_W1B);
    unsigned* s_p1b = reinterpret_cast<unsigned*>(sm + OFF_P1B);
    float*    s_b1  = sm + OFF_B1;
    float*    s_w2  = sm + OFF_W2;
    float*    s_pb1 = sm + OFF_PB1;
    float*    s_pw2 = sm + OFF_PW2;
    float*    s_sc  = sm + OFF_SC;

    const int tid = threadIdx.x;

    // stage att weights bf16x2: word j of row e = (W[e][2j], W[e][2j+1]); rows padded 8->12 words
    for (int i = tid; i < W1ROWS * 8; i += TPB) {
        const int e = i >> 3, j = i & 7;
        s_w1b[e * W1PADW + j] = f2bf2(att_w1[e * 16 + 2 * j], att_w1[e * 16 + 2 * j + 1]);
    }
    // stage pred weights bf16x2 (4 words per row, dense)
    for (int i = tid; i < P1ROWS * 4; i += TPB) {
        const int e = i >> 2, j = i & 3;
        s_p1b[i] = f2bf2(pred_w1[e * 8 + 2 * j], pred_w1[e * 8 + 2 * j + 1]);
    }
    if (tid < 16) { s_b1[tid] = att_b1[tid]; s_w2[tid] = att_w2[tid]; }
    if (tid < 8)  { s_pb1[tid] = pred_b1[tid]; s_pw2[tid] = pred_w2[tid]; }
    if (tid == 0) {
        s_sc[0] = att_b2[0]; s_sc[1] = pred_b2[0];
        s_sc[2] = cls_w[0];  s_sc[3] = cls_w[1];
        s_sc[4] = cls_b[0];  s_sc[5] = cls_b[1];
    }
    __syncthreads();

    const unsigned lane = tid & 31;
    const int warp = tid >> 5;
    const int oidx = (int)((lane >> 2) & 7);
    const float b1v0 = s_b1[oidx],  b1v1 = s_b1[8 + oidx];
    const float w2v0 = s_w2[oidx],  w2v1 = s_w2[8 + oidx];
    const float pb1v = s_pb1[oidx], pw2v = s_pw2[oidx];
    const float attb2 = s_sc[0], predb2 = s_sc[1];
    const float clsd  = s_sc[3] - s_sc[2];
    const float clsbd = s_sc[5] - s_sc[4];

    const int stride = GRID * WPB;
    int b = blockIdx.x * WPB + warp;
    if (b >= B_) return;

    // ---- pipeline prologue: indices + member/item rows for first b ----
    int gid = group_inputs[b];
    int iid = item_inputs[b];
    int4 mi4 = *reinterpret_cast<const int4*>(group_members + (size_t)gid * 4);

    float m0[8], m1[8], m2[8], m3[8], it[8];
    {
        const float* u0 = user_emb + (size_t)mi4.x * D_ + lane;
        const float* u1 = user_emb + (size_t)mi4.y * D_ + lane;
        const float* u2 = user_emb + (size_t)mi4.z * D_ + lane;
        const float* u3 = user_emb + (size_t)mi4.w * D_ + lane;
        const float* ip = item_emb + (size_t)iid   * D_ + lane;
#pragma unroll
        for (int k = 0; k < 8; k++) {
            m0[k] = u0[32 * k]; m1[k] = u1[32 * k];
            m2[k] = u2[32 * k]; m3[k] = u3[32 * k];
            it[k] = ip[32 * k];
        }
    }

    while (true) {
        // group-row load issued early (latency covered by attention phase)
        const float* gep = group_emb + (size_t)gid * D_ + lane;
        float ge[8];
#pragma unroll
        for (int k = 0; k < 8; k++) ge[k] = gep[32 * k];

        // prefetch next-b index chain (overlaps attention FFMA phase)
        const int bn = b + stride;
        const bool has_next = (bn < B_);
        int ngid = 0, niid = 0;
        int4 nmi4 = make_int4(0, 0, 0, 0);
        if (has_next) {
            ngid = group_inputs[bn];
            niid = item_inputs[bn];
            nmi4 = *reinterpret_cast<const int4*>(group_members + (size_t)ngid * 4);
        }

        // ---- attention MLP (bf16 weights) in two feature halves ----
        float lp0 = 0.f, lp1 = 0.f, lp2 = 0.f, lp3 = 0.f;
#pragma unroll
        for (int H = 0; H < 2; H++) {
            unsigned long long a0[4], a1[4], a2[4], a3[4], ia[4];
#pragma unroll
            for (int fp = 0; fp < 4; fp++) { a0[fp] = 0; a1[fp] = 0; a2[fp] = 0; a3[fp] = 0; ia[fp] = 0; }
#pragma unroll
            for (int k = 0; k < 8; k++) {
                const int e = (int)lane + 32 * k;
                // one LDS.128 per operand: 4 bf16x2 words = 8 features
                const uint4 qm = *reinterpret_cast<const uint4*>(s_w1b + e * W1PADW + 4 * H);
                const uint4 qI = *reinterpret_cast<const uint4*>(s_w1b + (e + 256) * W1PADW + 4 * H);
                const unsigned long long v0 = splat2(m0[k]);
                const unsigned long long v1 = splat2(m1[k]);
                const unsigned long long v2 = splat2(m2[k]);
                const unsigned long long v3 = splat2(m3[k]);
                const unsigned long long vi = splat2(it[k]);
                const unsigned long long w0 = bf2f2(qm.x), w1 = bf2f2(qm.y);
                const unsigned long long w2 = bf2f2(qm.z), w3 = bf2f2(qm.w);
                ffma2(a0[0], v0, w0); ffma2(a0[1], v0, w1); ffma2(a0[2], v0, w2); ffma2(a0[3], v0, w3);
                ffma2(a1[0], v1, w0); ffma2(a1[1], v1, w1); ffma2(a1[2], v1, w2); ffma2(a1[3], v1, w3);
                ffma2(a2[0], v2, w0); ffma2(a2[1], v2, w1); ffma2(a2[2], v2, w2); ffma2(a2[3], v2, w3);
                ffma2(a3[0], v3, w0); ffma2(a3[1], v3, w1); ffma2(a3[2], v3, w2); ffma2(a3[3], v3, w3);
                ffma2(ia[0], vi, bf2f2(qI.x)); ffma2(ia[1], vi, bf2f2(qI.y));
                ffma2(ia[2], vi, bf2f2(qI.z)); ffma2(ia[3], vi, bf2f2(qI.w));
            }
            const float b1v = H ? b1v1 : b1v0;
            const float w2v = H ? w2v1 : w2v0;
#pragma unroll
            for (int s = 0; s < 4; s++) {
                const unsigned long long* a = (s == 0) ? a0 : (s == 1) ? a1 : (s == 2) ? a2 : a3;
                float p[8];
#pragma unroll
                for (int fp = 0; fp < 4; fp++) {
                    p[2 * fp]     = lo2(a[fp]) + lo2(ia[fp]);
                    p[2 * fp + 1] = hi2(a[fp]) + hi2(ia[fp]);
                }
                const float hs = dreduce8(p, lane);
                const float h = fmaxf(hs + b1v, 0.0f);
                const float c = h * w2v;
                if      (s == 0) lp0 += c;
                else if (s == 1) lp1 += c;
                else if (s == 2) lp2 += c;
                else             lp3 += c;
            }
        }
        float logits[4];
        logits[0] = xsum3(lp0) + attb2;
        logits[1] = xsum3(lp1) + attb2;
        logits[2] = xsum3(lp2) + attb2;
        logits[3] = xsum3(lp3) + attb2;

        // softmax + first-argmax (strict > matches jnp.argmax tie rule)
        float mx = logits[0]; int mi = 0;
#pragma unroll
        for (int s = 1; s < 4; s++) if (logits[s] > mx) { mx = logits[s]; mi = s; }
        const float e0 = __expf(logits[0] - mx), e1 = __expf(logits[1] - mx);
        const float e2 = __expf(logits[2] - mx), e3 = __expf(logits[3] - mx);
        const float inv = 1.0f / (e0 + e1 + e2 + e3);
        const float wt0 = e0 * inv, wt1 = e1 * inv, wt2 = e2 * inv, wt3 = e3 * inv;
        const float wmx = (mi == 0) ? wt0 : (mi == 1) ? wt1 : (mi == 2) ? wt2 : wt3;
        const bool pc = (wmx * clsd + clsbd) > 0.0f;

        // g = (leader | weighted) + group_emb  (last use of m0..m3)
        float g[8];
#pragma unroll
        for (int k = 0; k < 8; k++) {
            const float ws = wt0 * m0[k] + wt1 * m1[k] + wt2 * m2[k] + wt3 * m3[k];
            const float ld = (mi == 0) ? m0[k] : (mi == 1) ? m1[k] : (mi == 2) ? m2[k] : m3[k];
            g[k] = (pc ? ld : ws) + ge[k];
        }

        // ---- issue next-b row loads NOW (m regs dead; overlaps pred MLP) ----
        float nit[8];
        if (has_next) {
            const float* u0 = user_emb + (size_t)nmi4.x * D_ + lane;
            const float* u1 = user_emb + (size_t)nmi4.y * D_ + lane;
            const float* u2 = user_emb + (size_t)nmi4.z * D_ + lane;
            const float* u3 = user_emb + (size_t)nmi4.w * D_ + lane;
            const float* ip = item_emb + (size_t)niid   * D_ + lane;
#pragma unroll
            for (int k = 0; k < 8; k++) {
                m0[k] = u0[32 * k]; m1[k] = u1[32 * k];
                m2[k] = u2[32 * k]; m3[k] = u3[32 * k];
                nit[k] = ip[32 * k];
            }
        }

        // ---- prediction MLP (bf16 weights) ----
        unsigned long long pa[4] = {0, 0, 0, 0};
#pragma unroll
        for (int k = 0; k < 8; k++) {
            const int e = (int)lane + 32 * k;
            const uint4 qe = *reinterpret_cast<const uint4*>(s_p1b + 4 * e);
            const uint4 qg = *reinterpret_cast<const uint4*>(s_p1b + 4 * (e + 256));
            const uint4 qi = *reinterpret_cast<const uint4*>(s_p1b + 4 * (e + 512));
            const unsigned long long ve = splat2(g[k] * it[k]);
            const unsigned long long vg = splat2(g[k]);
            const unsigned long long vi = splat2(it[k]);
            ffma2(pa[0], ve, bf2f2(qe.x)); ffma2(pa[1], ve, bf2f2(qe.y));
            ffma2(pa[2], ve, bf2f2(qe.z)); ffma2(pa[3], ve, bf2f2(qe.w));
            ffma2(pa[0], vg, bf2f2(qg.x)); ffma2(pa[1], vg, bf2f2(qg.y));
            ffma2(pa[2], vg, bf2f2(qg.z)); ffma2(pa[3], vg, bf2f2(qg.w));
            ffma2(pa[0], vi, bf2f2(qi.x)); ffma2(pa[1], vi, bf2f2(qi.y));
            ffma2(pa[2], vi, bf2f2(qi.z)); ffma2(pa[3], vi, bf2f2(qi.w));
        }
        float q[8];
#pragma unroll
        for (int op = 0; op < 4; op++) { q[2 * op] = lo2(pa[op]); q[2 * op + 1] = hi2(pa[op]); }
        const float ps = dreduce8(q, lane);
        const float h2 = fmaxf(ps + pb1v, 0.0f);
        const float z = xsum3(h2 * pw2v) + predb2;
        const float y = 1.0f / (1.0f + __expf(-z));

        if (lane == 0) {
            out[b] = y;
            out[5 * B_ + b] = pc ? 1.0f : 0.0f;
        }
        if (lane < 4) {
            const float w = (lane == 0) ? wt0 : (lane == 1) ? wt1 : (lane == 2) ? wt2 : wt3;
            out[B_ + 4 * b + (int)lane] = w;
        }

        if (!has_next) break;
#pragma unroll
        for (int k = 0; k < 8; k++) it[k] = nit[k];
        gid = ngid; iid = niid; b = bn;
    }
}

extern "C" void kernel_launch(void* const* d_in, const int* in_sizes, int n_in,
                              void* d_out, int out_size) {
    cudaFuncSetAttribute(agree_kernel, cudaFuncAttributeMaxDynamicSharedMemorySize, SMEM_BYTES);
    agree_kernel<<<GRID, TPB, SMEM_BYTES>>>(
        (const int*)d_in[0], (const int*)d_in[1], (const int*)d_in[2],
        (const float*)d_in[3], (const float*)d_in[4], (const float*)d_in[5],
        (const float*)d_in[6], (const float*)d_in[7], (const float*)d_in[8], (const float*)d_in[9],
        (const float*)d_in[10], (const float*)d_in[11], (const float*)d_in[12], (const float*)d_in[13],
        (const float*)d_in[14], (const float*)d_in[15],
        (float*)d_out);
}

// round 12
// speedup vs baseline: 1.3261x; 1.3261x over previous
#include <cuda_runtime.h>

// ---------------- problem constants ----------------
constexpr int B_  = 65536;
constexpr int D_  = 256;
constexpr int W1ROWS = 512;         // att_w1 bf16x2: 8 words used, padded to 12 (3x16B units, gcd(3,8)=1 -> conflict-free)
constexpr int W1PADW = 12;
constexpr int P1ROWS = 768;         // pred_w1 bf16x2: 4 words (16B) per row

constexpr int TPB  = 256;           // 8 warps / block
constexpr int WPB  = TPB / 32;
constexpr int GRID = 296;           // 2 blocks/SM -> 16 warps/SM

// dynamic shared layout (word offsets)
constexpr int OFF_W1B = 0;                         // 512*12 = 6144 words
constexpr int OFF_P1B = OFF_W1B + W1ROWS * W1PADW; // 6144
constexpr int OFF_B1  = OFF_P1B + P1ROWS * 4;      // 9216
constexpr int OFF_W2  = OFF_B1 + 16;
constexpr int OFF_PB1 = OFF_W2 + 16;
constexpr int OFF_PW2 = OFF_PB1 + 8;
constexpr int OFF_SC  = OFF_PW2 + 8;
constexpr int SMEM_WORDS = OFF_SC + 8;             // 9272
constexpr int SMEM_BYTES = SMEM_WORDS * 4;         // ~36.2 KB; 2 blocks = 72.5KB/SM

// ---------------- packed f32x2 helpers ----------------
__device__ __forceinline__ unsigned long long splat2(float x) {
    unsigned long long r;
    asm("mov.b64 %0, {%1, %1};" : "=l"(r) : "f"(x));
    return r;
}
__device__ __forceinline__ unsigned long long pack2u(unsigned x, unsigned y) {
    unsigned long long r;
    asm("mov.b64 %0, {%1, %2};" : "=l"(r) : "r"(x), "r"(y));
    return r;
}
__device__ __forceinline__ void ffma2(unsigned long long& d, unsigned long long a, unsigned long long b) {
    asm("fma.rn.f32x2 %0, %1, %2, %0;" : "+l"(d) : "l"(a), "l"(b));
}
__device__ __forceinline__ unsigned long long addx2(unsigned long long a, unsigned long long b) {
    unsigned long long r;
    asm("add.rn.f32x2 %0, %1, %2;" : "=l"(r) : "l"(a), "l"(b));
    return r;
}
__device__ __forceinline__ float lo2(unsigned long long v) { return __uint_as_float((unsigned)v); }
__device__ __forceinline__ float hi2(unsigned long long v) { return __uint_as_float((unsigned)(v >> 32)); }

// bf16x2 word -> packed f32x2 (lo bf16 -> lo f32, hi bf16 -> hi f32)
__device__ __forceinline__ unsigned long long bf2f2(unsigned w) {
    return pack2u(w << 16, w & 0xffff0000u);
}
__device__ __forceinline__ unsigned f2bf2(float f0, float f1) {
    unsigned r;
    asm("cvt.rn.bf16x2.f32 %0, %1, %2;" : "=r"(r) : "f"(f1), "f"(f0));
    return r;
}

// Merged distributed reduce: lane holds v[0..15] u64 = partials for
// (member m = idx>>2, feature pair fp = idx&3), features (2fp, 2fp+1) packed.
// Returns the full 32-lane scalar sum for output (m = lane>>3, f = lane&7),
// exactly one output per lane. 31 SHFL total.
__device__ __forceinline__ float dreduce32(unsigned long long* v, unsigned lane) {
    const unsigned FULL = 0xffffffffu;
    const bool b4 = (lane & 16), b3 = (lane & 8), b2 = (lane & 4);
    const bool b1q = (lane & 2), b0 = (lane & 1);
#pragma unroll
    for (int j = 0; j < 8; j++) {           // m-high (idx bit3) <- lane bit4
        unsigned long long send = b4 ? v[j] : v[j + 8];
        unsigned long long r = __shfl_xor_sync(FULL, send, 16);
        v[j] = addx2(b4 ? v[j + 8] : v[j], r);
    }
#pragma unroll
    for (int j = 0; j < 4; j++) {           // m-low <- lane bit3
        unsigned long long send = b3 ? v[j] : v[j + 4];
        unsigned long long r = __shfl_xor_sync(FULL, send, 8);
        v[j] = addx2(b3 ? v[j + 4] : v[j], r);
    }
#pragma unroll
    for (int j = 0; j < 2; j++) {           // fp-high <- lane bit2
        unsigned long long send = b2 ? v[j] : v[j + 2];
        unsigned long long r = __shfl_xor_sync(FULL, send, 4);
        v[j] = addx2(b2 ? v[j + 2] : v[j], r);
    }
    {                                       // fp-low <- lane bit1
        unsigned long long send = b1q ? v[0] : v[1];
        unsigned long long r = __shfl_xor_sync(FULL, send, 2);
        v[0] = addx2(b1q ? v[1] : v[0], r);
    }
    // lo/hi split <- lane bit0: partner needs the opposite half
    const float send = b0 ? lo2(v[0]) : hi2(v[0]);
    const float r = __shfl_xor_sync(FULL, send, 1);
    return (b0 ? hi2(v[0]) : lo2(v[0])) + r;
}

// Distributed reduce over 8 values (pred path): lane holds p[0..7] partials;
// returns the full 32-lane sum for o=(lane>>2)&7, replicated per 4-lane group.
__device__ __forceinline__ float dreduce8(float* p, unsigned lane) {
    const unsigned FULL = 0xffffffffu;
    const bool b4 = (lane & 16), b3 = (lane & 8), b2 = (lane & 4);
#pragma unroll
    for (int j = 0; j < 4; j++) {
        float send = b4 ? p[j] : p[j + 4];
        float r = __shfl_xor_sync(FULL, send, 16);
        p[j] = (b4 ? p[j + 4] : p[j]) + r;
    }
#pragma unroll
    for (int j = 0; j < 2; j++) {
        float send = b3 ? p[j] : p[j + 2];
        float r = __shfl_xor_sync(FULL, send, 8);
        p[j] = (b3 ? p[j + 2] : p[j]) + r;
    }
    {
        float send = b2 ? p[0] : p[1];
        float r = __shfl_xor_sync(FULL, send, 4);
        p[0] = (b2 ? p[1] : p[0]) + r;
    }
    p[0] += __shfl_xor_sync(FULL, p[0], 2);
    p[0] += __shfl_xor_sync(FULL, p[0], 1);
    return p[0];
}

// Sum across the 8 o-groups; input identical within each 4-lane o-group.
__device__ __forceinline__ float xsum3(float v) {
    v += __shfl_xor_sync(0xffffffffu, v, 4);
    v += __shfl_xor_sync(0xffffffffu, v, 8);
    v += __shfl_xor_sync(0xffffffffu, v, 16);
    return v;
}

__global__ __launch_bounds__(TPB, 2) void agree_kernel(
    const int*   __restrict__ group_inputs,
    const int*   __restrict__ item_inputs,
    const int*   __restrict__ group_members,
    const float* __restrict__ user_emb,
    const float* __restrict__ item_emb,
    const float* __restrict__ group_emb,
    const float* __restrict__ att_w1,
    const float* __restrict__ att_b1,
    const float* __restrict__ att_w2,
    const float* __restrict__ att_b2,
    const float* __restrict__ cls_w,
    const float* __restrict__ cls_b,
    const float* __restrict__ pred_w1,
    const float* __restrict__ pred_b1,
    const float* __restrict__ pred_w2,
    const float* __restrict__ pred_b2,
    float* __restrict__ out)
{
    extern __shared__ float sm[];
    unsigned* s_w1b = reinterpret_cast<unsigned*>(sm + OFF_W1B);
    unsigned* s_p1b = reinterpret_cast<unsigned*>(sm + OFF_P1B);
    float*    s_b1  = sm + OFF_B1;
    float*    s_w2  = sm + OFF_W2;
    float*    s_pb1 = sm + OFF_PB1;
    float*    s_pw2 = sm + OFF_PW2;
    float*    s_sc  = sm + OFF_SC;

    const int tid = threadIdx.x;

    // stage att weights bf16x2: word j of row e = (W[e][2j], W[e][2j+1]); rows padded 8->12 words
    for (int i = tid; i < W1ROWS * 8; i += TPB) {
        const int e = i >> 3, j = i & 7;
        s_w1b[e * W1PADW + j] = f2bf2(att_w1[e * 16 + 2 * j], att_w1[e * 16 + 2 * j + 1]);
    }
    // stage pred weights bf16x2 (4 words per row, dense)
    for (int i = tid; i < P1ROWS * 4; i += TPB) {
        const int e = i >> 2, j = i & 3;
        s_p1b[i] = f2bf2(pred_w1[e * 8 + 2 * j], pred_w1[e * 8 + 2 * j + 1]);
    }
    if (tid < 16) { s_b1[tid] = att_b1[tid]; s_w2[tid] = att_w2[tid]; }
    if (tid < 8)  { s_pb1[tid] = pred_b1[tid]; s_pw2[tid] = pred_w2[tid]; }
    if (tid == 0) {
        s_sc[0] = att_b2[0]; s_sc[1] = pred_b2[0];
        s_sc[2] = cls_w[0];  s_sc[3] = cls_w[1];
        s_sc[4] = cls_b[0];  s_sc[5] = cls_b[1];
    }
    __syncthreads();

    const unsigned lane = tid & 31;
    const int warp = tid >> 5;
    // attention consts: one (m, f) output per lane after dreduce32 -> f = lane&7
    const int fidx = (int)(lane & 7);
    const float b1v0 = s_b1[fidx],  b1v1 = s_b1[8 + fidx];
    const float w2v0 = s_w2[fidx],  w2v1 = s_w2[8 + fidx];
    // pred consts: dreduce8 layout -> o = (lane>>2)&7
    const int oidx = (int)((lane >> 2) & 7);
    const float pb1v = s_pb1[oidx], pw2v = s_pw2[oidx];
    const float attb2 = s_sc[0], predb2 = s_sc[1];
    const float clsd  = s_sc[3] - s_sc[2];
    const float clsbd = s_sc[5] - s_sc[4];

    const int stride = GRID * WPB;
    int b = blockIdx.x * WPB + warp;

    // ---- pipeline prologue: indices + member/item rows for first b ----
    int gid = group_inputs[b];
    int iid = item_inputs[b];
    int4 mi4 = *reinterpret_cast<const int4*>(group_members + (size_t)gid * 4);

    float m0[8], m1[8], m2[8], m3[8], it[8];
    {
        const float* u0 = user_emb + (size_t)mi4.x * D_ + lane;
        const float* u1 = user_emb + (size_t)mi4.y * D_ + lane;
        const float* u2 = user_emb + (size_t)mi4.z * D_ + lane;
        const float* u3 = user_emb + (size_t)mi4.w * D_ + lane;
        const float* ip = item_emb + (size_t)iid   * D_ + lane;
#pragma unroll
        for (int k = 0; k < 8; k++) {
            m0[k] = u0[32 * k]; m1[k] = u1[32 * k];
            m2[k] = u2[32 * k]; m3[k] = u3[32 * k];
            it[k] = ip[32 * k];
        }
    }

    while (true) {
        // group-row load issued early (latency covered by attention phase)
        const float* gep = group_emb + (size_t)gid * D_ + lane;
        float ge[8];
#pragma unroll
        for (int k = 0; k < 8; k++) ge[k] = gep[32 * k];

        // prefetch next-b index chain (overlaps attention FFMA phase)
        const int bn = b + stride;
        const bool has_next = (bn < B_);
        int ngid = 0, niid = 0;
        int4 nmi4 = make_int4(0, 0, 0, 0);
        if (has_next) {
            ngid = group_inputs[bn];
            niid = item_inputs[bn];
            nmi4 = *reinterpret_cast<const int4*>(group_members + (size_t)ngid * 4);
        }

        // ---- attention MLP (bf16 weights) in two feature halves ----
        // lc accumulates (relu(h)+b1)*w2 per lane for (m = lane>>3, f = lane&7)
        float lc = 0.f;
#pragma unroll
        for (int H = 0; H < 2; H++) {
            unsigned long long a0[4], a1[4], a2[4], a3[4], ia[4];
#pragma unroll
            for (int fp = 0; fp < 4; fp++) { a0[fp] = 0; a1[fp] = 0; a2[fp] = 0; a3[fp] = 0; ia[fp] = 0; }
#pragma unroll
            for (int k = 0; k < 8; k++) {
                const int e = (int)lane + 32 * k;
                // one LDS.128 per operand: 4 bf16x2 words = 8 features
                const uint4 qm = *reinterpret_cast<const uint4*>(s_w1b + e * W1PADW + 4 * H);
                const uint4 qI = *reinterpret_cast<const uint4*>(s_w1b + (e + 256) * W1PADW + 4 * H);
                const unsigned long long v0 = splat2(m0[k]);
                const unsigned long long v1 = splat2(m1[k]);
                const unsigned long long v2 = splat2(m2[k]);
                const unsigned long long v3 = splat2(m3[k]);
                const unsigned long long vi = splat2(it[k]);
                const unsigned long long w0 = bf2f2(qm.x), w1 = bf2f2(qm.y);
                const unsigned long long w2 = bf2f2(qm.z), w3 = bf2f2(qm.w);
                ffma2(a0[0], v0, w0); ffma2(a0[1], v0, w1); ffma2(a0[2], v0, w2); ffma2(a0[3], v0, w3);
                ffma2(a1[0], v1, w0); ffma2(a1[1], v1, w1); ffma2(a1[2], v1, w2); ffma2(a1[3], v1, w3);
                ffma2(a2[0], v2, w0); ffma2(a2[1], v2, w1); ffma2(a2[2], v2, w2); ffma2(a2[3], v2, w3);
                ffma2(a3[0], v3, w0); ffma2(a3[1], v3, w1); ffma2(a3[2], v3, w2); ffma2(a3[3], v3, w3);
                ffma2(ia[0], vi, bf2f2(qI.x)); ffma2(ia[1], vi, bf2f2(qI.y));
                ffma2(ia[2], vi, bf2f2(qI.z)); ffma2(ia[3], vi, bf2f2(qI.w));
            }
            // merge item half, then one merged tree for all 4 members x 8 features
            unsigned long long v[16];
#pragma unroll
            for (int fp = 0; fp < 4; fp++) {
                v[0 * 4 + fp] = addx2(a0[fp], ia[fp]);
                v[1 * 4 + fp] = addx2(a1[fp], ia[fp]);
                v[2 * 4 + fp] = addx2(a2[fp], ia[fp]);
                v[3 * 4 + fp] = addx2(a3[fp], ia[fp]);
            }
            const float hs = dreduce32(v, lane);
            const float b1v = H ? b1v1 : b1v0;
            const float w2v = H ? w2v1 : w2v0;
            lc += fmaxf(hs + b1v, 0.0f) * w2v;
        }
        // sum the 8 features within each member group (lanes m*8..m*8+7)
        lc += __shfl_xor_sync(0xffffffffu, lc, 1);
        lc += __shfl_xor_sync(0xffffffffu, lc, 2);
        lc += __shfl_xor_sync(0xffffffffu, lc, 4);
        float logits[4];
        logits[0] = __shfl_sync(0xffffffffu, lc, 0)  + attb2;
        logits[1] = __shfl_sync(0xffffffffu, lc, 8)  + attb2;
        logits[2] = __shfl_sync(0xffffffffu, lc, 16) + attb2;
        logits[3] = __shfl_sync(0xffffffffu, lc, 24) + attb2;

        // softmax + first-argmax (strict > matches jnp.argmax tie rule)
        float mx = logits[0]; int mi = 0;
#pragma unroll
        for (int s = 1; s < 4; s++) if (logits[s] > mx) { mx = logits[s]; mi = s; }
        const float e0 = __expf(logits[0] - mx), e1 = __expf(logits[1] - mx);
        const float e2 = __expf(logits[2] - mx), e3 = __expf(logits[3] - mx);
        const float inv = 1.0f / (e0 + e1 + e2 + e3);
        const float wt0 = e0 * inv, wt1 = e1 * inv, wt2 = e2 * inv, wt3 = e3 * inv;
        const float wmx = (mi == 0) ? wt0 : (mi == 1) ? wt1 : (mi == 2) ? wt2 : wt3;
        const bool pc = (wmx * clsd + clsbd) > 0.0f;

        // g = (leader | weighted) + group_emb  (last use of m0..m3)
        float g[8];
#pragma unroll
        for (int k = 0; k < 8; k++) {
            const float ws = wt0 * m0[k] + wt1 * m1[k] + wt2 * m2[k] + wt3 * m3[k];
            const float ld = (mi == 0) ? m0[k] : (mi == 1) ? m1[k] : (mi == 2) ? m2[k] : m3[k];
            g[k] = (pc ? ld : ws) + ge[k];
        }

        // ---- issue next-b row loads NOW (m regs dead; overlaps pred MLP) ----
        float nit[8];
        if (has_next) {
            const float* u0 = user_emb + (size_t)nmi4.x * D_ + lane;
            const float* u1 = user_emb + (size_t)nmi4.y * D_ + lane;
            const float* u2 = user_emb + (size_t)nmi4.z * D_ + lane;
            const float* u3 = user_emb + (size_t)nmi4.w * D_ + lane;
            const float* ip = item_emb + (size_t)niid   * D_ + lane;
#pragma unroll
            for (int k = 0; k < 8; k++) {
                m0[k] = u0[32 * k]; m1[k] = u1[32 * k];
                m2[k] = u2[32 * k]; m3[k] = u3[32 * k];
                nit[k] = ip[32 * k];
            }
        }

        // ---- prediction MLP (bf16 weights) ----
        unsigned long long pa[4] = {0, 0, 0, 0};
#pragma unroll
        for (int k = 0; k < 8; k++) {
            const int e = (int)lane + 32 * k;
            const uint4 qe = *reinterpret_cast<const uint4*>(s_p1b + 4 * e);
            const uint4 qg = *reinterpret_cast<const uint4*>(s_p1b + 4 * (e + 256));
            const uint4 qi = *reinterpret_cast<const uint4*>(s_p1b + 4 * (e + 512));
            const unsigned long long ve = splat2(g[k] * it[k]);
            const unsigned long long vg = splat2(g[k]);
            const unsigned long long vi = splat2(it[k]);
            ffma2(pa[0], ve, bf2f2(qe.x)); ffma2(pa[1], ve, bf2f2(qe.y));
            ffma2(pa[2], ve, bf2f2(qe.z)); ffma2(pa[3], ve, bf2f2(qe.w));
            ffma2(pa[0], vg, bf2f2(qg.x)); ffma2(pa[1], vg, bf2f2(qg.y));
            ffma2(pa[2], vg, bf2f2(qg.z)); ffma2(pa[3], vg, bf2f2(qg.w));
            ffma2(pa[0], vi, bf2f2(qi.x)); ffma2(pa[1], vi, bf2f2(qi.y));
            ffma2(pa[2], vi, bf2f2(qi.z)); ffma2(pa[3], vi, bf2f2(qi.w));
        }
        float q[8];
#pragma unroll
        for (int op = 0; op < 4; op++) { q[2 * op] = lo2(pa[op]); q[2 * op + 1] = hi2(pa[op]); }
        const float ps = dreduce8(q, lane);
        const float h2 = fmaxf(ps + pb1v, 0.0f);
        const float z = xsum3(h2 * pw2v) + predb2;
        const float y = 1.0f / (1.0f + __expf(-z));

        if (lane == 0) {
            out[b] = y;
            out[5 * B_ + b] = pc ? 1.0f : 0.0f;
        }
        if (lane < 4) {
            const float w = (lane == 0) ? wt0 : (lane == 1) ? wt1 : (lane == 2) ? wt2 : wt3;
            out[B_ + 4 * b + (int)lane] = w;
        }

        if (!has_next) break;
#pragma unroll
        for (int k = 0; k < 8; k++) it[k] = nit[k];
        gid = ngid; iid = niid; b = bn;
    }
}

extern "C" void kernel_launch(void* const* d_in, const int* in_sizes, int n_in,
                              void* d_out, int out_size) {
    cudaFuncSetAttribute(agree_kernel, cudaFuncAttributeMaxDynamicSharedMemorySize, SMEM_BYTES);
    agree_kernel<<<GRID, TPB, SMEM_BYTES>>>(
        (const int*)d_in[0], (const int*)d_in[1], (const int*)d_in[2],
        (const float*)d_in[3], (const float*)d_in[4], (const float*)d_in[5],
        (const float*)d_in[6], (const float*)d_in[7], (const float*)d_in[8], (const float*)d_in[9],
        (const float*)d_in[10], (const float*)d_in[11], (const float*)d_in[12], (const float*)d_in[13],
        (const float*)d_in[14], (const float*)d_in[15],
        (float*)d_out);
}